// round 3
// baseline (speedup 1.0000x reference)
#include <cuda_runtime.h>
#include <math.h>

#define NROWS_MAX 500000
#define C 128
#define CV 32          // C/4 float4 per row
#define HID 8
#define NB 16

// Scratch (no allocations allowed)
__device__ float g_sums[NB][C];
__device__ float g_counts[NB];
__device__ float g_gate[NB][C];

// ---------------------------------------------------------------------------
// 0) zero accumulators (must run every launch for determinism)
// ---------------------------------------------------------------------------
__global__ void zero_kernel() {
    int t = threadIdx.x;  // one block of 2048? no: use 2048 elems / 256 threads
    for (int i = t; i < NB * C; i += blockDim.x) ((float*)g_sums)[i] = 0.0f;
    if (t < NB) g_counts[t] = 0.0f;
}

// ---------------------------------------------------------------------------
// 1) segment sum: register accumulation, flush on batch change (sorted idx)
//    One warp owns one row per step: lane l -> float4 slot l (16B), row stride 8.
// ---------------------------------------------------------------------------
__global__ __launch_bounds__(256) void reduce_kernel(
    const float4* __restrict__ x, const int* __restrict__ bidx,
    int n, int rows_per_block)
{
    int row0 = blockIdx.x * rows_per_block;
    int row1 = row0 + rows_per_block;
    if (row1 > n) row1 = n;
    if (row0 >= row1) return;

    int warp = threadIdx.x >> 5;
    int lane = threadIdx.x & 31;

    float4 acc = make_float4(0.f, 0.f, 0.f, 0.f);
    float cnt = 0.f;
    int cur_b = -1;

    for (int r = row0 + warp; r < row1; r += 8) {
        int b = bidx[r];                    // broadcast load (uniform in warp)
        if (b != cur_b) {
            if (cur_b >= 0) {               // flush previous batch
                float* dst = &g_sums[cur_b][lane * 4];
                atomicAdd(dst + 0, acc.x);
                atomicAdd(dst + 1, acc.y);
                atomicAdd(dst + 2, acc.z);
                atomicAdd(dst + 3, acc.w);
                if (lane == 0) atomicAdd(&g_counts[cur_b], cnt);
            }
            cur_b = b;
            acc = make_float4(0.f, 0.f, 0.f, 0.f);
            cnt = 0.f;
        }
        float4 v = x[(size_t)r * CV + lane];
        acc.x += v.x; acc.y += v.y; acc.z += v.z; acc.w += v.w;
        if (lane == 0) cnt += 1.0f;
    }
    if (cur_b >= 0) {
        float* dst = &g_sums[cur_b][lane * 4];
        atomicAdd(dst + 0, acc.x);
        atomicAdd(dst + 1, acc.y);
        atomicAdd(dst + 2, acc.z);
        atomicAdd(dst + 3, acc.w);
        if (lane == 0) atomicAdd(&g_counts[cur_b], cnt);
    }
}

// ---------------------------------------------------------------------------
// 2) tiny MLP: mean -> Linear(128,8) -> ReLU -> Linear(8,128) -> sigmoid
//    One block, 128 threads. Total work ~ 16*(128*8 + 8*128) FLOPs = trivial.
// ---------------------------------------------------------------------------
__global__ __launch_bounds__(128) void mlp_kernel(
    const float* __restrict__ W1, const float* __restrict__ b1,
    const float* __restrict__ W2, const float* __restrict__ b2)
{
    __shared__ float s_mean[NB][C];
    __shared__ float s_h[NB][HID];

    int t = threadIdx.x;  // 0..127

    for (int i = t; i < NB * C; i += 128) {
        int b = i / C, c = i % C;
        float cn = g_counts[b];
        cn = fmaxf(cn, 1.0f);
        s_mean[b][c] = g_sums[b][c] / cn;
    }
    __syncthreads();

    // h[b][j], 16*8 = 128 outputs -> one per thread
    {
        int b = t / HID, j = t % HID;
        float acc = b1[j];
        #pragma unroll 8
        for (int c = 0; c < C; c++) acc += s_mean[b][c] * W1[c * HID + j];
        s_h[b][j] = fmaxf(acc, 0.0f);
    }
    __syncthreads();

    // gate[b][c], thread t -> column c=t, loop over b
    {
        int c = t;
        float w2c[HID];
        #pragma unroll
        for (int j = 0; j < HID; j++) w2c[j] = W2[j * C + c];
        float bias = b2[c];
        for (int b = 0; b < NB; b++) {
            float acc = bias;
            #pragma unroll
            for (int j = 0; j < HID; j++) acc += s_h[b][j] * w2c[j];
            g_gate[b][c] = 1.0f / (1.0f + expf(-acc));
        }
    }
}

// ---------------------------------------------------------------------------
// 3) apply gate: out[r][c] = x[r][c] * gate[bidx[r]][c]   (512 MB traffic)
// ---------------------------------------------------------------------------
__global__ __launch_bounds__(256) void apply_kernel(
    const float4* __restrict__ x, const int* __restrict__ bidx,
    float4* __restrict__ out, int n)
{
    __shared__ float4 s_gate[NB][CV];  // 8 KB
    for (int i = threadIdx.x; i < NB * CV; i += blockDim.x)
        ((float4*)s_gate)[i] = ((const float4*)g_gate)[i];
    __syncthreads();

    int lane = threadIdx.x & 31;
    int gwarp = (blockIdx.x * blockDim.x + threadIdx.x) >> 5;
    int nwarps = (gridDim.x * blockDim.x) >> 5;

    for (int r = gwarp; r < n; r += nwarps) {
        int b = bidx[r];
        float4 v = x[(size_t)r * CV + lane];
        float4 g = s_gate[b][lane];
        v.x *= g.x; v.y *= g.y; v.z *= g.z; v.w *= g.w;
        out[(size_t)r * CV + lane] = v;
    }
}

// ---------------------------------------------------------------------------
extern "C" void kernel_launch(void* const* d_in, const int* in_sizes, int n_in,
                              void* d_out, int out_size)
{
    const float* x    = (const float*)d_in[0];
    const int*   bidx = (const int*)d_in[1];
    const float* W1   = (const float*)d_in[2];
    const float* b1   = (const float*)d_in[3];
    const float* W2   = (const float*)d_in[4];
    const float* b2   = (const float*)d_in[5];
    float* out = (float*)d_out;

    int n = in_sizes[1];  // number of rows (batch_idx has N entries)

    zero_kernel<<<1, 256>>>();

    const int RED_BLOCKS = 592;  // 4 waves of 148 SMs
    int rows_per_block = (n + RED_BLOCKS - 1) / RED_BLOCKS;
    reduce_kernel<<<RED_BLOCKS, 256>>>((const float4*)x, bidx, n, rows_per_block);

    mlp_kernel<<<1, 128>>>(W1, b1, W2, b2);

    const int APPLY_BLOCKS = 1184;  // 8 waves
    apply_kernel<<<APPLY_BLOCKS, 256>>>((const float4*)x, bidx, (float4*)out, n);
}

// round 4
// speedup vs baseline: 1.1191x; 1.1191x over previous
#include <cuda_runtime.h>
#include <math.h>

#define C 128
#define CV 32          // C/4 float4 per row
#define HID 8
#define NB 16

// Scratch (no allocations allowed)
__device__ float g_sums[NB][C];
__device__ float g_counts[NB];
__device__ float g_gate[NB][C];

// ---------------------------------------------------------------------------
// 0) zero accumulators (must run every launch for determinism)
// ---------------------------------------------------------------------------
__global__ void zero_kernel() {
    int t = threadIdx.x;
    for (int i = t; i < NB * C; i += blockDim.x) ((float*)g_sums)[i] = 0.0f;
    if (t < NB) g_counts[t] = 0.0f;
}

// ---------------------------------------------------------------------------
// 1) segment sum: register accumulation, flush on batch change (sorted idx).
//    One warp owns one row per step: lane l -> float4 slot l (16B).
//    Unrolled x4 with front-batched independent loads so MLP_p1 ~ 8 and the
//    DRAM latency (~380-577 cyc) is covered by in-flight loads, not occupancy.
// ---------------------------------------------------------------------------
__global__ __launch_bounds__(256) void reduce_kernel(
    const float4* __restrict__ x, const int* __restrict__ bidx,
    int n, int rows_per_block)
{
    int row0 = blockIdx.x * rows_per_block;
    int row1 = row0 + rows_per_block;
    if (row1 > n) row1 = n;
    if (row0 >= row1) return;

    int warp = threadIdx.x >> 5;
    int lane = threadIdx.x & 31;

    float4 acc = make_float4(0.f, 0.f, 0.f, 0.f);
    float cnt = 0.f;
    int cur_b = -1;

    auto flush = [&]() {
        float* dst = &g_sums[cur_b][lane * 4];
        atomicAdd(dst + 0, acc.x);
        atomicAdd(dst + 1, acc.y);
        atomicAdd(dst + 2, acc.z);
        atomicAdd(dst + 3, acc.w);
        if (lane == 0) atomicAdd(&g_counts[cur_b], cnt);
    };
    auto consume = [&](int b, const float4& v) {
        if (b != cur_b) {                 // rare: <=16 boundaries in whole input
            if (cur_b >= 0) flush();
            cur_b = b;
            acc = make_float4(0.f, 0.f, 0.f, 0.f);
            cnt = 0.f;
        }
        acc.x += v.x; acc.y += v.y; acc.z += v.z; acc.w += v.w;
        cnt += 1.0f;                      // only lane 0's value is used
    };

    int r = row0 + warp;
    // main loop: 4 rows in flight per warp
    for (; r + 24 < row1; r += 32) {
        int b0 = bidx[r];
        int b1 = bidx[r + 8];
        int b2 = bidx[r + 16];
        int b3 = bidx[r + 24];
        float4 v0 = x[(size_t)(r)      * CV + lane];
        float4 v1 = x[(size_t)(r + 8)  * CV + lane];
        float4 v2 = x[(size_t)(r + 16) * CV + lane];
        float4 v3 = x[(size_t)(r + 24) * CV + lane];
        consume(b0, v0);
        consume(b1, v1);
        consume(b2, v2);
        consume(b3, v3);
    }
    // remainder
    for (; r < row1; r += 8) {
        int b = bidx[r];
        float4 v = x[(size_t)r * CV + lane];
        consume(b, v);
    }
    if (cur_b >= 0) flush();
}

// ---------------------------------------------------------------------------
// 2) tiny MLP: mean -> Linear(128,8) -> ReLU -> Linear(8,128) -> sigmoid
// ---------------------------------------------------------------------------
__global__ __launch_bounds__(128) void mlp_kernel(
    const float* __restrict__ W1, const float* __restrict__ b1,
    const float* __restrict__ W2, const float* __restrict__ b2)
{
    __shared__ float s_mean[NB][C];
    __shared__ float s_h[NB][HID];

    int t = threadIdx.x;  // 0..127

    for (int i = t; i < NB * C; i += 128) {
        int b = i / C, c = i % C;
        float cn = fmaxf(g_counts[b], 1.0f);
        s_mean[b][c] = g_sums[b][c] / cn;
    }
    __syncthreads();

    {
        int b = t / HID, j = t % HID;
        float acc = b1[j];
        #pragma unroll 8
        for (int c = 0; c < C; c++) acc += s_mean[b][c] * W1[c * HID + j];
        s_h[b][j] = fmaxf(acc, 0.0f);
    }
    __syncthreads();

    {
        int c = t;
        float w2c[HID];
        #pragma unroll
        for (int j = 0; j < HID; j++) w2c[j] = W2[j * C + c];
        float bias = b2[c];
        for (int b = 0; b < NB; b++) {
            float acc = bias;
            #pragma unroll
            for (int j = 0; j < HID; j++) acc += s_h[b][j] * w2c[j];
            g_gate[b][c] = 1.0f / (1.0f + expf(-acc));
        }
    }
}

// ---------------------------------------------------------------------------
// 3) apply gate: out[r][c] = x[r][c] * gate[bidx[r]][c]   (512 MB traffic)
//    x2 unroll with front-batched loads.
// ---------------------------------------------------------------------------
__global__ __launch_bounds__(256) void apply_kernel(
    const float4* __restrict__ x, const int* __restrict__ bidx,
    float4* __restrict__ out, int n)
{
    __shared__ float4 s_gate[NB][CV];  // 8 KB
    for (int i = threadIdx.x; i < NB * CV; i += blockDim.x)
        ((float4*)s_gate)[i] = ((const float4*)g_gate)[i];
    __syncthreads();

    int lane = threadIdx.x & 31;
    int gwarp = (blockIdx.x * blockDim.x + threadIdx.x) >> 5;
    int nwarps = (gridDim.x * blockDim.x) >> 5;

    int r = gwarp;
    for (; r + nwarps < n; r += 2 * nwarps) {
        int r2 = r + nwarps;
        int b0 = bidx[r];
        int b1 = bidx[r2];
        float4 v0 = x[(size_t)r  * CV + lane];
        float4 v1 = x[(size_t)r2 * CV + lane];
        float4 g0 = s_gate[b0][lane];
        float4 g1 = s_gate[b1][lane];
        v0.x *= g0.x; v0.y *= g0.y; v0.z *= g0.z; v0.w *= g0.w;
        v1.x *= g1.x; v1.y *= g1.y; v1.z *= g1.z; v1.w *= g1.w;
        out[(size_t)r  * CV + lane] = v0;
        out[(size_t)r2 * CV + lane] = v1;
    }
    if (r < n) {
        int b = bidx[r];
        float4 v = x[(size_t)r * CV + lane];
        float4 g = s_gate[b][lane];
        v.x *= g.x; v.y *= g.y; v.z *= g.z; v.w *= g.w;
        out[(size_t)r * CV + lane] = v;
    }
}

// ---------------------------------------------------------------------------
extern "C" void kernel_launch(void* const* d_in, const int* in_sizes, int n_in,
                              void* d_out, int out_size)
{
    const float* x    = (const float*)d_in[0];
    const int*   bidx = (const int*)d_in[1];
    const float* W1   = (const float*)d_in[2];
    const float* b1   = (const float*)d_in[3];
    const float* W2   = (const float*)d_in[4];
    const float* b2   = (const float*)d_in[5];
    float* out = (float*)d_out;

    int n = in_sizes[1];  // number of rows (batch_idx has N entries)

    zero_kernel<<<1, 256>>>();

    const int RED_BLOCKS = 592;  // 4 waves of 148 SMs
    int rows_per_block = (n + RED_BLOCKS - 1) / RED_BLOCKS;
    reduce_kernel<<<RED_BLOCKS, 256>>>((const float4*)x, bidx, n, rows_per_block);

    mlp_kernel<<<1, 128>>>(W1, b1, W2, b2);

    const int APPLY_BLOCKS = 1184;  // 8 waves
    apply_kernel<<<APPLY_BLOCKS, 256>>>((const float4*)x, bidx, (float4*)out, n);
}